// round 9
// baseline (speedup 1.0000x reference)
#include <cuda_runtime.h>
#include <cuda_fp16.h>
#include <cstdint>

// ===================== Problem constants =====================
#define B_DIM 8192
#define P_DIM 24
#define Q_DIM 12
#define E_DIM 256
#define V_DIM 1000
#define LN_EPS 1e-5f

#define GEMM_CTAS 384          // 24 p * 16 m-slots (512 rows each, 256/half)
#define CAT_CTAS 192
#define TOK_PER_CAT_CTA 512    // 98304 / 192

#define W2T_BLKS 1536          // 8 x 8 x 24
#define H_BLKS   (P_DIM * 128) // 3072: one per (p, 64-row tile)

// fp16 transposed W2: [p][f][e], 3.1 MB static scratch
__device__ __half g_W2Th[P_DIM * E_DIM * E_DIM];
// fragment-packed fp16 H = gelu(x*W1+b1): [p][mt64(128)][ks(16)][mti(4)][lane(32)] uint4
__device__ uint4 g_Hfrag[P_DIM * 128 * 16 * 4 * 32];   // 100.7 MB static scratch

// ---- fast gelu: 0.5 t (1 + erf(t/sqrt2)), A&S 7.1.26 (|erf err| < 1.5e-7) ----
__device__ __forceinline__ float fast_gelu(float t) {
    const float z  = fabsf(t) * 0.70710678118654752f;
    const float k  = __fdividef(1.0f, fmaf(0.3275911f, z, 1.0f));
    float pk = fmaf(1.061405429f, k, -1.453152027f);
    pk = fmaf(pk, k, 1.421413741f);
    pk = fmaf(pk, k, -0.284496736f);
    pk = fmaf(pk, k, 0.254829592f);
    pk = pk * k;
    const float ez   = __expf(-z * z);
    const float erfv = fmaf(-pk, ez, 1.0f);          // erf(|t|/sqrt2)
    const float e    = (t >= 0.f) ? erfv : -erfv;
    return 0.5f * t * (1.0f + e);
}

// ===================== Prep kernel: w2t + H generation =====================
// blocks [0, W2T_BLKS): transpose+halve W2.  blocks [W2T_BLKS, +H_BLKS): H frags.
__global__ __launch_bounds__(256)
void prep_kernel(const float* __restrict__ W2,
                 const float* __restrict__ x_num,
                 const float* __restrict__ W1,
                 const float* __restrict__ b1) {
    __shared__ float sh[1056];
    const int tid = threadIdx.x;

    if (blockIdx.x < W2T_BLKS) {
        // ---- W2 transpose: W2[p][e][f] -> g_W2Th[p][f][e] ----
        float (*tile)[33] = (float(*)[33])sh;
        const int blk = blockIdx.x;
        const int f0 = (blk & 7) * 32;
        const int e0 = ((blk >> 3) & 7) * 32;
        const int p  = blk >> 6;
        const int tx = tid & 31, ty = tid >> 5;
        #pragma unroll
        for (int i = ty; i < 32; i += 8)
            tile[i][tx] = W2[((size_t)p * 256 + e0 + i) * 256 + f0 + tx];
        __syncthreads();
        #pragma unroll
        for (int i = ty; i < 32; i += 8)
            g_W2Th[((size_t)p * 256 + f0 + i) * 256 + e0 + tx] = __float2half_rn(tile[tx][i]);
        return;
    }

    // ---- H generation for one (p, mt64): 64 rows x 256 k, fragment-packed ----
    const int blk2 = blockIdx.x - W2T_BLKS;
    const int p    = blk2 >> 7;
    const int mt64 = blk2 & 127;

    float* xs  = sh;         // 64
    float* w1s = sh + 64;    // 256
    float* b1s = sh + 320;   // 256
    if (tid < 64) xs[tid] = x_num[(size_t)(mt64 * 64 + tid) * P_DIM + p];
    w1s[tid] = W1[p * 256 + tid];
    b1s[tid] = b1[p * 256 + tid];
    __syncthreads();

    const int lane = tid & 31;
    const int w    = tid >> 5;            // 0..7
    uint4* hbase = g_Hfrag + ((size_t)(p * 128 + mt64) * 16) * 4 * 32;

    #pragma unroll
    for (int ksi = 0; ksi < 2; ksi++) {
        const int ks = w * 2 + ksi;
        const int kbase = ks * 16 + (lane & 3) * 2;
        #pragma unroll
        for (int mti = 0; mti < 4; mti++) {
            const float xm0 = xs[mti * 16 + (lane >> 2)];
            const float xm1 = xs[mti * 16 + (lane >> 2) + 8];
            uint32_t r[4];
            #pragma unroll
            for (int reg = 0; reg < 4; reg++) {
                const float xm = (reg & 1) ? xm1 : xm0;
                const int k = kbase + (reg & 2) * 4;
                float h0 = fast_gelu(fmaf(xm, w1s[k],     b1s[k]));
                float h1 = fast_gelu(fmaf(xm, w1s[k + 1], b1s[k + 1]));
                __half2 hv = __floats2half2_rn(h0, h1);
                r[reg] = *reinterpret_cast<uint32_t*>(&hv);
            }
            hbase[((size_t)ks * 4 + mti) * 32 + lane] = make_uint4(r[0], r[1], r[2], r[3]);
        }
    }
}

// ===================== Fused kernel: GEMM(+LN) halves + cat path =====================
// SMEM byte offsets
#define SM_B2   0        // 256 f
#define SM_G    1024     // 256 f
#define SM_BE   2048     // 256 f
#define SM_STAT 3072     // 2 halves x 64 rows x 16 f = 8192 B (ends 11264)
#define SM_B    16384    // 131072 B: B frags [ks(16)][ntp(16)][lane(32)][4] b32
#define GEMM_SMEM (16384 + 131072)   // 147456

#define HALF_BAR(id) asm volatile("bar.sync %0, %1;" :: "r"(id), "r"(256) : "memory")

__device__ __forceinline__ void mma16816(float* c, const uint32_t* a, const uint32_t* b) {
    asm volatile(
        "mma.sync.aligned.m16n8k16.row.col.f32.f16.f16.f32 "
        "{%0,%1,%2,%3}, {%4,%5,%6,%7}, {%8,%9}, {%0,%1,%2,%3};\n"
        : "+f"(c[0]), "+f"(c[1]), "+f"(c[2]), "+f"(c[3])
        : "r"(a[0]), "r"(a[1]), "r"(a[2]), "r"(a[3]), "r"(b[0]), "r"(b[1]));
}

__global__ __launch_bounds__(512, 1)
void fused_kernel(const int*   __restrict__ x_cat,
                  const float* __restrict__ b2,
                  const float* __restrict__ emb,
                  const float* __restrict__ gamma,
                  const float* __restrict__ beta,
                  float* __restrict__ out) {
    const int tid  = threadIdx.x;
    const int lane = tid & 31;
    const int warp = tid >> 5;       // 0..15

    // ================= CAT PATH =================
    if (blockIdx.x >= GEMM_CTAS) {
        const int blk2 = blockIdx.x - GEMM_CTAS;
        const float4* g4  = (const float4*)gamma;
        const float4* be4 = (const float4*)beta;
        float4 g0 = g4[lane], g1 = g4[lane + 32];
        float4 e0 = be4[lane], e1 = be4[lane + 32];

        #pragma unroll 1
        for (int it = 0; it < TOK_PER_CAT_CTA / 16; it++) {
            const int tok = blk2 * TOK_PER_CAT_CTA + it * 16 + warp;
            const int b = tok / Q_DIM;
            const int q = tok % Q_DIM;
            const int idx = x_cat[(size_t)b * Q_DIM + q];
            const float4* src = (const float4*)(emb + ((size_t)q * V_DIM + idx) * E_DIM);
            float4 v0 = src[lane];
            float4 v1 = src[lane + 32];

            float sum = v0.x + v0.y + v0.z + v0.w + v1.x + v1.y + v1.z + v1.w;
            float sq  = v0.x * v0.x + v0.y * v0.y + v0.z * v0.z + v0.w * v0.w
                      + v1.x * v1.x + v1.y * v1.y + v1.z * v1.z + v1.w * v1.w;
            #pragma unroll
            for (int off = 16; off > 0; off >>= 1) {
                sum += __shfl_xor_sync(0xFFFFFFFFu, sum, off);
                sq  += __shfl_xor_sync(0xFFFFFFFFu, sq, off);
            }
            const float mu   = sum * (1.0f / 256.0f);
            const float var  = sq * (1.0f / 256.0f) - mu * mu;
            const float rstd = rsqrtf(var + LN_EPS);

            float4 r0, r1;
            r0.x = (v0.x - mu) * rstd * g0.x + e0.x;
            r0.y = (v0.y - mu) * rstd * g0.y + e0.y;
            r0.z = (v0.z - mu) * rstd * g0.z + e0.z;
            r0.w = (v0.w - mu) * rstd * g0.w + e0.w;
            r1.x = (v1.x - mu) * rstd * g1.x + e1.x;
            r1.y = (v1.y - mu) * rstd * g1.y + e1.y;
            r1.z = (v1.z - mu) * rstd * g1.z + e1.z;
            r1.w = (v1.w - mu) * rstd * g1.w + e1.w;

            float4* dst = (float4*)(out + ((size_t)b * 36 + 24 + q) * E_DIM);
            dst[lane] = r0;
            dst[lane + 32] = r1;
        }
        return;
    }

    // ================= GEMM PATH =================
    extern __shared__ char smem[];
    const int p     = blockIdx.x >> 4;   // 0..23
    const int mslot = blockIdx.x & 15;   // 0..15

    float* b2s = (float*)(smem + SM_B2);
    float* gs  = (float*)(smem + SM_G);
    float* bes = (float*)(smem + SM_BE);

    if (tid < 256) {
        b2s[tid] = b2[p * 256 + tid];
        gs[tid]  = gamma[tid];
        bes[tid] = beta[tid];
    }

    // ---- Stage B frags ONCE (read-only afterwards): warp = ks ----
    {
        const uint32_t* w2pu = (const uint32_t*)(g_W2Th + (size_t)p * 65536);
        uint4* bbuf4 = (uint4*)(smem + SM_B);
        const int ks = warp;
        const int ne_base = (lane >> 2);
        const int kh0 = ks * 8 + (lane & 3);
        const int kh1 = kh0 + 4;
        #pragma unroll
        for (int ntp = 0; ntp < 16; ntp++) {
            const int n_e = (2 * ntp) * 8 + ne_base;
            const int n_o = n_e + 8;
            uint4 v;
            v.x = w2pu[n_e * 128 + kh0];
            v.y = w2pu[n_e * 128 + kh1];
            v.z = w2pu[n_o * 128 + kh0];
            v.w = w2pu[n_o * 128 + kh1];
            bbuf4[(ks * 16 + ntp) * 32 + lane] = v;
        }
    }
    __syncthreads();   // B + consts visible; last block-wide barrier

    // ---- Half-CTA setup ----
    const int hh  = warp >> 3;          // half id 0/1
    const int wh  = warp & 7;           // warp within half (n octet, 32 cols)
    const int barid = 1 + hh;

    float* stat_h = (float*)(smem + SM_STAT) + hh * 1024;     // [64][16] floats

    float2 b2v[4];
    #pragma unroll
    for (int ntl = 0; ntl < 4; ntl++)
        b2v[ntl] = *(float2*)&b2s[wh * 32 + ntl * 8 + (lane & 3) * 2];

    const uint4* bfrag = (const uint4*)(smem + SM_B);

    // ---- Tile loop: 4 tiles of 64 rows per half ----
    for (int t = 0; t < 4; t++) {
        const int mt64 = mslot * 8 + hh * 4 + t;
        const int m0   = mt64 * 64;
        const uint4* aglob = g_Hfrag + ((size_t)(p * 128 + mt64) * 16) * 4 * 32;

        float acc[4][4][4];
        #pragma unroll
        for (int i = 0; i < 4; i++)
            #pragma unroll
            for (int j = 0; j < 4; j++)
                #pragma unroll
                for (int r = 0; r < 4; r++) acc[i][j][r] = 0.f;

        // ---- Mainloop: A frags from gmem (double-buffered), B from SMEM ----
        uint4 ab[2][4];
        #pragma unroll
        for (int mti = 0; mti < 4; mti++)
            ab[0][mti] = aglob[(size_t)mti * 32 + lane];

        #pragma unroll
        for (int ks = 0; ks < 16; ks++) {
            if (ks < 15) {
                #pragma unroll
                for (int mti = 0; mti < 4; mti++)
                    ab[(ks + 1) & 1][mti] = aglob[((size_t)(ks + 1) * 4 + mti) * 32 + lane];
            }
            uint32_t a[4][4];
            #pragma unroll
            for (int mti = 0; mti < 4; mti++) {
                const uint4 v = ab[ks & 1][mti];
                a[mti][0] = v.x; a[mti][1] = v.y; a[mti][2] = v.z; a[mti][3] = v.w;
            }
            #pragma unroll
            for (int i = 0; i < 2; i++) {
                uint4 bv4 = bfrag[(ks * 16 + wh * 2 + i) * 32 + lane];
                uint32_t b0[2] = {bv4.x, bv4.y};
                uint32_t b1r[2] = {bv4.z, bv4.w};
                #pragma unroll
                for (int mti = 0; mti < 4; mti++) {
                    mma16816(acc[mti][i * 2],     a[mti], b0);
                    mma16816(acc[mti][i * 2 + 1], a[mti], b1r);
                }
            }
        }

        // ---- Epilogue: +b2, LayerNorm ----
        #pragma unroll
        for (int mti = 0; mti < 4; mti++)
            #pragma unroll
            for (int ntl = 0; ntl < 4; ntl++) {
                acc[mti][ntl][0] += b2v[ntl].x;
                acc[mti][ntl][1] += b2v[ntl].y;
                acc[mti][ntl][2] += b2v[ntl].x;
                acc[mti][ntl][3] += b2v[ntl].y;
            }

        #pragma unroll
        for (int mti = 0; mti < 4; mti++)
            #pragma unroll
            for (int h = 0; h < 2; h++) {
                float s = 0.f, q = 0.f;
                #pragma unroll
                for (int ntl = 0; ntl < 4; ntl++) {
                    float v0 = acc[mti][ntl][h * 2];
                    float v1 = acc[mti][ntl][h * 2 + 1];
                    s += v0 + v1;
                    q += v0 * v0 + v1 * v1;
                }
                s += __shfl_xor_sync(0xFFFFFFFFu, s, 1);
                q += __shfl_xor_sync(0xFFFFFFFFu, q, 1);
                s += __shfl_xor_sync(0xFFFFFFFFu, s, 2);
                q += __shfl_xor_sync(0xFFFFFFFFu, q, 2);
                if ((lane & 3) == 0) {
                    const int row = mti * 16 + (lane >> 2) + h * 8;
                    *(float2*)&stat_h[row * 16 + wh * 2] = make_float2(s, q);
                }
            }
        HALF_BAR(barid);

        #pragma unroll
        for (int mti = 0; mti < 4; mti++)
            #pragma unroll
            for (int h = 0; h < 2; h++) {
                const int row = mti * 16 + (lane >> 2) + h * 8;
                float sum = 0.f, sq = 0.f;
                #pragma unroll
                for (int j = 0; j < 4; j++) {
                    float4 v = *(float4*)&stat_h[row * 16 + j * 4];
                    sum += v.x + v.z;
                    sq  += v.y + v.w;
                }
                const float mu   = sum * (1.0f / 256.0f);
                const float var  = sq * (1.0f / 256.0f) - mu * mu;
                const float rstd = rsqrtf(var + LN_EPS);

                float* orow = out + (((size_t)(m0 + row) * 36 + p) * 256);
                #pragma unroll
                for (int ntl = 0; ntl < 4; ntl++) {
                    const int col = wh * 32 + ntl * 8 + (lane & 3) * 2;
                    const float2 gvv = *(float2*)&gs[col];
                    const float2 bvv = *(float2*)&bes[col];
                    float2 r;
                    r.x = (acc[mti][ntl][h * 2]     - mu) * rstd * gvv.x + bvv.x;
                    r.y = (acc[mti][ntl][h * 2 + 1] - mu) * rstd * gvv.y + bvv.y;
                    *(float2*)&orow[col] = r;
                }
            }
        HALF_BAR(barid);   // protect stat_h before next tile
    }
}

// ===================== Launch =====================
extern "C" void kernel_launch(void* const* d_in, const int* in_sizes, int n_in,
                              void* d_out, int out_size) {
    const float* x_num = (const float*)d_in[0];
    const int*   x_cat = (const int*)d_in[1];
    const float* W1    = (const float*)d_in[2];
    const float* b1    = (const float*)d_in[3];
    const float* W2    = (const float*)d_in[4];
    const float* b2    = (const float*)d_in[5];
    const float* emb   = (const float*)d_in[6];
    const float* gamma = (const float*)d_in[7];
    const float* beta  = (const float*)d_in[8];
    float* out = (float*)d_out;

    cudaFuncSetAttribute(fused_kernel,
                         cudaFuncAttributeMaxDynamicSharedMemorySize, GEMM_SMEM);

    prep_kernel<<<W2T_BLKS + H_BLKS, 256>>>(W2, x_num, W1, b1);
    fused_kernel<<<GEMM_CTAS + CAT_CTAS, 512, GEMM_SMEM>>>(
        x_cat, b2, emb, gamma, beta, out);
}

// round 10
// speedup vs baseline: 1.1259x; 1.1259x over previous
#include <cuda_runtime.h>
#include <cuda_fp16.h>
#include <cstdint>

// ===================== Problem constants =====================
#define B_DIM 8192
#define P_DIM 24
#define Q_DIM 12
#define E_DIM 256
#define V_DIM 1000
#define LN_EPS 1e-5f

#define GEMM_CTAS 384          // 24 p * 16 m-slots (512 rows each, 256/half)
#define CAT_CTAS 192
#define TOK_PER_CAT_CTA 512    // 98304 / 192

// fp16 transposed W2: [p][f][e]  (K-major B operand), 3.1 MB static scratch
__device__ __half g_W2Th[P_DIM * E_DIM * E_DIM];

// ===================== Kernel 0: transpose + halve W2 =====================
__global__ void w2t_kernel(const float* __restrict__ W2) {
    __shared__ float tile[32][33];
    int p  = blockIdx.z;
    int e0 = blockIdx.y * 32;
    int f0 = blockIdx.x * 32;
    int tx = threadIdx.x, ty = threadIdx.y;
    #pragma unroll
    for (int i = ty; i < 32; i += 8)
        tile[i][tx] = W2[((size_t)p * 256 + e0 + i) * 256 + f0 + tx];
    __syncthreads();
    #pragma unroll
    for (int i = ty; i < 32; i += 8) {
        float v = tile[tx][i];
        g_W2Th[((size_t)p * 256 + f0 + i) * 256 + e0 + tx] = __float2half_rn(v);
    }
}

// ---- fast gelu: 0.5 t (1 + erf(t/sqrt2)), A&S 7.1.26 (|erf err| < 1.5e-7) ----
// Validated round 9: rel_err identical (2.233e-4) to erff version.
__device__ __forceinline__ float fast_gelu(float t) {
    const float z  = fabsf(t) * 0.70710678118654752f;
    const float k  = __fdividef(1.0f, fmaf(0.3275911f, z, 1.0f));
    float pk = fmaf(1.061405429f, k, -1.453152027f);
    pk = fmaf(pk, k, 1.421413741f);
    pk = fmaf(pk, k, -0.284496736f);
    pk = fmaf(pk, k, 0.254829592f);
    pk = pk * k;
    const float ez   = __expf(-z * z);
    const float erfv = fmaf(-pk, ez, 1.0f);          // erf(|t|/sqrt2)
    const float e    = (t >= 0.f) ? erfv : -erfv;
    return 0.5f * t * (1.0f + e);
}

// ===================== Fused kernel: two independent 256-thread halves =====================
// SMEM byte offsets
#define SM_X    0        // 2 halves x 64 f = 512 B
#define SM_W1   1024     // 256 f
#define SM_B1   2048     // 256 f
#define SM_B2   3072     // 256 f
#define SM_G    4096     // 256 f
#define SM_BE   5120     // 256 f
#define SM_STAT 6144     // 2 halves x 64 rows x 16 f = 8192 B (ends 14336)
#define SM_A    16384    // 2 halves x 32768 B: A frags [ks(16)][mti(4)][lane(32)][4] b32
#define SM_B    81920    // 131072 B: B frags [ks(16)][ntp(16)][lane(32)][4] b32
#define GEMM_SMEM (81920 + 131072)   // 212992

#define HALF_BAR(id) asm volatile("bar.sync %0, %1;" :: "r"(id), "r"(256) : "memory")

__device__ __forceinline__ void mma16816(float* c, const uint32_t* a, const uint32_t* b) {
    asm volatile(
        "mma.sync.aligned.m16n8k16.row.col.f32.f16.f16.f32 "
        "{%0,%1,%2,%3}, {%4,%5,%6,%7}, {%8,%9}, {%0,%1,%2,%3};\n"
        : "+f"(c[0]), "+f"(c[1]), "+f"(c[2]), "+f"(c[3])
        : "r"(a[0]), "r"(a[1]), "r"(a[2]), "r"(a[3]), "r"(b[0]), "r"(b[1]));
}

__global__ __launch_bounds__(512, 1)
void fused_kernel(const float* __restrict__ x_num,
                  const int*   __restrict__ x_cat,
                  const float* __restrict__ W1,
                  const float* __restrict__ b1,
                  const float* __restrict__ b2,
                  const float* __restrict__ emb,
                  const float* __restrict__ gamma,
                  const float* __restrict__ beta,
                  float* __restrict__ out) {
    const int tid  = threadIdx.x;
    const int lane = tid & 31;
    const int warp = tid >> 5;       // 0..15

    // ================= CAT PATH =================
    if (blockIdx.x >= GEMM_CTAS) {
        const int blk2 = blockIdx.x - GEMM_CTAS;
        const float4* g4  = (const float4*)gamma;
        const float4* be4 = (const float4*)beta;
        float4 g0 = g4[lane], g1 = g4[lane + 32];
        float4 e0 = be4[lane], e1 = be4[lane + 32];

        #pragma unroll 1
        for (int it = 0; it < TOK_PER_CAT_CTA / 16; it++) {
            const int tok = blk2 * TOK_PER_CAT_CTA + it * 16 + warp;
            const int b = tok / Q_DIM;
            const int q = tok % Q_DIM;
            const int idx = x_cat[(size_t)b * Q_DIM + q];
            const float4* src = (const float4*)(emb + ((size_t)q * V_DIM + idx) * E_DIM);
            float4 v0 = src[lane];
            float4 v1 = src[lane + 32];

            float sum = v0.x + v0.y + v0.z + v0.w + v1.x + v1.y + v1.z + v1.w;
            float sq  = v0.x * v0.x + v0.y * v0.y + v0.z * v0.z + v0.w * v0.w
                      + v1.x * v1.x + v1.y * v1.y + v1.z * v1.z + v1.w * v1.w;
            #pragma unroll
            for (int off = 16; off > 0; off >>= 1) {
                sum += __shfl_xor_sync(0xFFFFFFFFu, sum, off);
                sq  += __shfl_xor_sync(0xFFFFFFFFu, sq, off);
            }
            const float mu   = sum * (1.0f / 256.0f);
            const float var  = sq * (1.0f / 256.0f) - mu * mu;
            const float rstd = rsqrtf(var + LN_EPS);

            float4 r0, r1;
            r0.x = (v0.x - mu) * rstd * g0.x + e0.x;
            r0.y = (v0.y - mu) * rstd * g0.y + e0.y;
            r0.z = (v0.z - mu) * rstd * g0.z + e0.z;
            r0.w = (v0.w - mu) * rstd * g0.w + e0.w;
            r1.x = (v1.x - mu) * rstd * g1.x + e1.x;
            r1.y = (v1.y - mu) * rstd * g1.y + e1.y;
            r1.z = (v1.z - mu) * rstd * g1.z + e1.z;
            r1.w = (v1.w - mu) * rstd * g1.w + e1.w;

            float4* dst = (float4*)(out + ((size_t)b * 36 + 24 + q) * E_DIM);
            dst[lane] = r0;
            dst[lane + 32] = r1;
        }
        return;
    }

    // ================= GEMM PATH =================
    extern __shared__ char smem[];
    const int p     = blockIdx.x >> 4;   // 0..23
    const int mslot = blockIdx.x & 15;   // 0..15

    float* w1s = (float*)(smem + SM_W1);
    float* b1s = (float*)(smem + SM_B1);
    float* b2s = (float*)(smem + SM_B2);
    float* gs  = (float*)(smem + SM_G);
    float* bes = (float*)(smem + SM_BE);

    if (tid < 256) {
        w1s[tid] = W1[p * 256 + tid];
        b1s[tid] = b1[p * 256 + tid];
        b2s[tid] = b2[p * 256 + tid];
        gs[tid]  = gamma[tid];
        bes[tid] = beta[tid];
    }

    // ---- Stage B frags ONCE (read-only afterwards): warp = ks ----
    {
        const uint32_t* w2pu = (const uint32_t*)(g_W2Th + (size_t)p * 65536);
        uint4* bbuf4 = (uint4*)(smem + SM_B);
        const int ks = warp;
        const int ne_base = (lane >> 2);
        const int kh0 = ks * 8 + (lane & 3);
        const int kh1 = kh0 + 4;
        #pragma unroll
        for (int ntp = 0; ntp < 16; ntp++) {
            const int n_e = (2 * ntp) * 8 + ne_base;
            const int n_o = n_e + 8;
            uint4 v;
            v.x = w2pu[n_e * 128 + kh0];
            v.y = w2pu[n_e * 128 + kh1];
            v.z = w2pu[n_o * 128 + kh0];
            v.w = w2pu[n_o * 128 + kh1];
            bbuf4[(ks * 16 + ntp) * 32 + lane] = v;
        }
    }
    __syncthreads();   // B + consts visible to both halves; last block-wide barrier

    // ---- Half-CTA setup ----
    const int hh  = warp >> 3;          // half id 0/1
    const int wh  = warp & 7;           // warp within half (n octet, 32 cols)
    const int barid = 1 + hh;
    const int tidh = tid & 255;

    float* xs_h   = (float*)(smem + SM_X) + hh * 64;
    float* stat_h = (float*)(smem + SM_STAT) + hh * 1024;     // [64][16] floats
    char*  abuf_h = smem + SM_A + hh * 32768;

    float2 b2v[4];
    #pragma unroll
    for (int ntl = 0; ntl < 4; ntl++)
        b2v[ntl] = *(float2*)&b2s[wh * 32 + ntl * 8 + (lane & 3) * 2];

    const uint4* bfrag = (const uint4*)(smem + SM_B);
    const uint4* afrag = (const uint4*)abuf_h;

    // ---- Tile loop: 4 tiles of 64 rows per half ----
    for (int t = 0; t < 4; t++) {
        const int m0 = (mslot * 8 + hh * 4 + t) * 64;

        if (tidh < 64) xs_h[tidh] = x_num[(size_t)(m0 + tidh) * P_DIM + p];
        HALF_BAR(barid);

        // ---- Prologue: gelu(x*W1+b1) -> A frags; warp covers ks = wh, wh+8 ----
        #pragma unroll
        for (int kk = 0; kk < 2; kk++) {
            const int ks = wh + kk * 8;
            const int kbase = ks * 16 + (lane & 3) * 2;
            #pragma unroll
            for (int mti = 0; mti < 4; mti++) {
                const float xm0 = xs_h[mti * 16 + (lane >> 2)];
                const float xm1 = xs_h[mti * 16 + (lane >> 2) + 8];
                uint32_t r[4];
                #pragma unroll
                for (int reg = 0; reg < 4; reg++) {
                    const float xm = (reg & 1) ? xm1 : xm0;
                    const int k = kbase + (reg & 2) * 4;
                    float h0 = fast_gelu(fmaf(xm, w1s[k],     b1s[k]));
                    float h1 = fast_gelu(fmaf(xm, w1s[k + 1], b1s[k + 1]));
                    __half2 hv = __floats2half2_rn(h0, h1);
                    r[reg] = *reinterpret_cast<uint32_t*>(&hv);
                }
                *(uint4*)(abuf_h + ((ks * 4 + mti) * 32 + lane) * 16) =
                    make_uint4(r[0], r[1], r[2], r[3]);
            }
        }
        HALF_BAR(barid);

        // ---- Mainloop: warp tile 64 rows x 32 cols ----
        float acc[4][4][4];
        #pragma unroll
        for (int i = 0; i < 4; i++)
            #pragma unroll
            for (int j = 0; j < 4; j++)
                #pragma unroll
                for (int r = 0; r < 4; r++) acc[i][j][r] = 0.f;

        #pragma unroll
        for (int ks = 0; ks < 16; ks++) {
            uint32_t a[4][4];
            #pragma unroll
            for (int mti = 0; mti < 4; mti++) {
                uint4 v = afrag[(ks * 4 + mti) * 32 + lane];
                a[mti][0] = v.x; a[mti][1] = v.y; a[mti][2] = v.z; a[mti][3] = v.w;
            }
            #pragma unroll
            for (int i = 0; i < 2; i++) {
                uint4 bv4 = bfrag[(ks * 16 + wh * 2 + i) * 32 + lane];
                uint32_t b0[2] = {bv4.x, bv4.y};
                uint32_t b1r[2] = {bv4.z, bv4.w};
                #pragma unroll
                for (int mti = 0; mti < 4; mti++) {
                    mma16816(acc[mti][i * 2],     a[mti], b0);
                    mma16816(acc[mti][i * 2 + 1], a[mti], b1r);
                }
            }
        }

        // ---- Epilogue: +b2, LayerNorm ----
        #pragma unroll
        for (int mti = 0; mti < 4; mti++)
            #pragma unroll
            for (int ntl = 0; ntl < 4; ntl++) {
                acc[mti][ntl][0] += b2v[ntl].x;
                acc[mti][ntl][1] += b2v[ntl].y;
                acc[mti][ntl][2] += b2v[ntl].x;
                acc[mti][ntl][3] += b2v[ntl].y;
            }

        #pragma unroll
        for (int mti = 0; mti < 4; mti++)
            #pragma unroll
            for (int h = 0; h < 2; h++) {
                float s = 0.f, q = 0.f;
                #pragma unroll
                for (int ntl = 0; ntl < 4; ntl++) {
                    float v0 = acc[mti][ntl][h * 2];
                    float v1 = acc[mti][ntl][h * 2 + 1];
                    s += v0 + v1;
                    q += v0 * v0 + v1 * v1;
                }
                s += __shfl_xor_sync(0xFFFFFFFFu, s, 1);
                q += __shfl_xor_sync(0xFFFFFFFFu, q, 1);
                s += __shfl_xor_sync(0xFFFFFFFFu, s, 2);
                q += __shfl_xor_sync(0xFFFFFFFFu, q, 2);
                if ((lane & 3) == 0) {
                    const int row = mti * 16 + (lane >> 2) + h * 8;
                    *(float2*)&stat_h[row * 16 + wh * 2] = make_float2(s, q);
                }
            }
        HALF_BAR(barid);

        #pragma unroll
        for (int mti = 0; mti < 4; mti++)
            #pragma unroll
            for (int h = 0; h < 2; h++) {
                const int row = mti * 16 + (lane >> 2) + h * 8;
                float sum = 0.f, sq = 0.f;
                #pragma unroll
                for (int j = 0; j < 4; j++) {
                    float4 v = *(float4*)&stat_h[row * 16 + j * 4];
                    sum += v.x + v.z;
                    sq  += v.y + v.w;
                }
                const float mu   = sum * (1.0f / 256.0f);
                const float var  = sq * (1.0f / 256.0f) - mu * mu;
                const float rstd = rsqrtf(var + LN_EPS);

                float* orow = out + (((size_t)(m0 + row) * 36 + p) * 256);
                #pragma unroll
                for (int ntl = 0; ntl < 4; ntl++) {
                    const int col = wh * 32 + ntl * 8 + (lane & 3) * 2;
                    const float2 gvv = *(float2*)&gs[col];
                    const float2 bvv = *(float2*)&bes[col];
                    float2 r;
                    r.x = (acc[mti][ntl][h * 2]     - mu) * rstd * gvv.x + bvv.x;
                    r.y = (acc[mti][ntl][h * 2 + 1] - mu) * rstd * gvv.y + bvv.y;
                    *(float2*)&orow[col] = r;
                }
            }
        HALF_BAR(barid);   // protect xs_h / abuf_h / stat_h before next tile
    }
}

// ===================== Launch =====================
extern "C" void kernel_launch(void* const* d_in, const int* in_sizes, int n_in,
                              void* d_out, int out_size) {
    const float* x_num = (const float*)d_in[0];
    const int*   x_cat = (const int*)d_in[1];
    const float* W1    = (const float*)d_in[2];
    const float* b1    = (const float*)d_in[3];
    const float* W2    = (const float*)d_in[4];
    const float* b2    = (const float*)d_in[5];
    const float* emb   = (const float*)d_in[6];
    const float* gamma = (const float*)d_in[7];
    const float* beta  = (const float*)d_in[8];
    float* out = (float*)d_out;

    cudaFuncSetAttribute(fused_kernel,
                         cudaFuncAttributeMaxDynamicSharedMemorySize, GEMM_SMEM);

    w2t_kernel<<<dim3(8, 8, 24), dim3(32, 8)>>>(W2);
    fused_kernel<<<GEMM_CTAS + CAT_CTAS, 512, GEMM_SMEM>>>(
        x_num, x_cat, W1, b1, b2, emb, gamma, beta, out);
}

// round 11
// speedup vs baseline: 1.1504x; 1.0218x over previous
#include <cuda_runtime.h>
#include <cuda_fp16.h>
#include <cstdint>

// ===================== Problem constants =====================
#define B_DIM 8192
#define P_DIM 24
#define Q_DIM 12
#define E_DIM 256
#define V_DIM 1000
#define LN_EPS 1e-5f

#define GEMM_CTAS 768          // 24 p * 32 mslots; each CTA: 4 tiles of 64 rows
#define CAT_CTAS 384
#define TOK_PER_CAT_CTA 256    // 98304 / 384

// fp16 transposed W2: [p][f][e], intermediate
__device__ __half g_W2Th[P_DIM * E_DIM * E_DIM];
// fragment-packed W2: [p][ks(16)][ntp(16)][lane(32)] uint4  (3.1 MB)
__device__ uint4 g_W2Tf[P_DIM * 16 * 16 * 32];

// ===================== Kernel 0: transpose + halve W2 =====================
__global__ void w2t_kernel(const float* __restrict__ W2) {
    __shared__ float tile[32][33];
    int p  = blockIdx.z;
    int e0 = blockIdx.y * 32;
    int f0 = blockIdx.x * 32;
    int tx = threadIdx.x, ty = threadIdx.y;
    #pragma unroll
    for (int i = ty; i < 32; i += 8)
        tile[i][tx] = W2[((size_t)p * 256 + e0 + i) * 256 + f0 + tx];
    __syncthreads();
    #pragma unroll
    for (int i = ty; i < 32; i += 8) {
        float v = tile[tx][i];
        g_W2Th[((size_t)p * 256 + f0 + i) * 256 + e0 + tx] = __float2half_rn(v);
    }
}

// ===================== Kernel 1: pack W2 fragments =====================
__global__ __launch_bounds__(256)
void pack_kernel() {
    const int p    = blockIdx.x;
    const int lane = threadIdx.x & 31;
    const int warp = threadIdx.x >> 5;   // 0..7
    const uint32_t* w2pu = (const uint32_t*)(g_W2Th + (size_t)p * 65536);
    uint4* dstb = g_W2Tf + (size_t)p * 8192;
    #pragma unroll
    for (int kk = 0; kk < 2; kk++) {
        const int ks = warp * 2 + kk;
        const int ne_base = lane >> 2;
        const int kh0 = ks * 8 + (lane & 3);
        const int kh1 = kh0 + 4;
        #pragma unroll
        for (int ntp = 0; ntp < 16; ntp++) {
            const int n_e = 2 * ntp * 8 + ne_base;
            const int n_o = n_e + 8;
            uint4 v;
            v.x = w2pu[n_e * 128 + kh0];
            v.y = w2pu[n_e * 128 + kh1];
            v.z = w2pu[n_o * 128 + kh0];
            v.w = w2pu[n_o * 128 + kh1];
            dstb[(ks * 16 + ntp) * 32 + lane] = v;
        }
    }
}

// ---- fast gelu (validated: rel_err identical to erff version) ----
__device__ __forceinline__ float fast_gelu(float t) {
    const float z  = fabsf(t) * 0.70710678118654752f;
    const float k  = __fdividef(1.0f, fmaf(0.3275911f, z, 1.0f));
    float pk = fmaf(1.061405429f, k, -1.453152027f);
    pk = fmaf(pk, k, 1.421413741f);
    pk = fmaf(pk, k, -0.284496736f);
    pk = fmaf(pk, k, 0.254829592f);
    pk = pk * k;
    const float ez   = __expf(-z * z);
    const float erfv = fmaf(-pk, ez, 1.0f);
    const float e    = (t >= 0.f) ? erfv : -erfv;
    return 0.5f * t * (1.0f + e);
}

// ===================== Fused kernel: 256 threads, 2 CTAs/SM =====================
// SMEM byte offsets
#define SM_X    0        // 64 f
#define SM_W1   1024     // 256 f
#define SM_B1   2048
#define SM_B2   3072
#define SM_G    4096
#define SM_BE   5120
#define SM_STAT 6144     // 64 rows x 16 f = 4096 B (ends 10240)
#define SM_A    12288    // 32768 B : A frags [ks(16)][mti(4)][lane(32)] uint4
#define SM_BUF  45056    // 2 x 32768 B : B ring, chunk = [ksl(4)][ntp(16)][lane(32)] uint4
#define GEMM_SMEM 110592

__device__ __forceinline__ void mma16816(float* c, const uint32_t* a, const uint32_t* b) {
    asm volatile(
        "mma.sync.aligned.m16n8k16.row.col.f32.f16.f16.f32 "
        "{%0,%1,%2,%3}, {%4,%5,%6,%7}, {%8,%9}, {%0,%1,%2,%3};\n"
        : "+f"(c[0]), "+f"(c[1]), "+f"(c[2]), "+f"(c[3])
        : "r"(a[0]), "r"(a[1]), "r"(a[2]), "r"(a[3]), "r"(b[0]), "r"(b[1]));
}

// stage full chunk c into buf (pre-loop use)
__device__ __forceinline__ void stage_full(const uint4* __restrict__ w2f, uint4* buf,
                                           int c, int warp, int lane) {
    const int ksl = warp & 3;
    const int ntp0 = (warp >> 2) * 8;
    const uint4* src = w2f + (size_t)(c * 4 + ksl) * 512 + ntp0 * 32 + lane;
    uint4* dst = buf + (ksl * 16 + ntp0) * 32 + lane;
    #pragma unroll
    for (int i = 0; i < 8; i++)
        dst[i * 32] = src[i * 32];
}

// mma over chunk c (4 ks) from bbuf; optionally stage chunk cs into sbuf (4+4 interleaved)
template <bool STAGE>
__device__ __forceinline__ void mma_chunk(float acc[4][4][4],
                                          const uint4* __restrict__ afrag,
                                          const uint4* __restrict__ bbuf,
                                          int c, int warp, int lane,
                                          const uint4* __restrict__ w2f,
                                          uint4* sbuf, int cs) {
    const int ksl_s = warp & 3;
    const int ntp0  = (warp >> 2) * 8;
    const uint4* src = w2f + (size_t)(cs * 4 + ksl_s) * 512 + ntp0 * 32 + lane;
    uint4* dst = sbuf + (ksl_s * 16 + ntp0) * 32 + lane;

    #pragma unroll
    for (int hf = 0; hf < 2; hf++) {
        uint4 r[4];
        if (STAGE) {
            #pragma unroll
            for (int i = 0; i < 4; i++) r[i] = src[(hf * 4 + i) * 32];
        }
        #pragma unroll
        for (int kl = 0; kl < 2; kl++) {
            const int ksl = hf * 2 + kl;
            const int ks  = c * 4 + ksl;
            uint32_t a[4][4];
            #pragma unroll
            for (int mti = 0; mti < 4; mti++) {
                uint4 v = afrag[(ks * 4 + mti) * 32 + lane];
                a[mti][0] = v.x; a[mti][1] = v.y; a[mti][2] = v.z; a[mti][3] = v.w;
            }
            #pragma unroll
            for (int i = 0; i < 2; i++) {
                uint4 bv4 = bbuf[(ksl * 16 + warp * 2 + i) * 32 + lane];
                uint32_t b0[2] = {bv4.x, bv4.y};
                uint32_t b1r[2] = {bv4.z, bv4.w};
                #pragma unroll
                for (int mti = 0; mti < 4; mti++) {
                    mma16816(acc[mti][i * 2],     a[mti], b0);
                    mma16816(acc[mti][i * 2 + 1], a[mti], b1r);
                }
            }
        }
        if (STAGE) {
            #pragma unroll
            for (int i = 0; i < 4; i++) dst[(hf * 4 + i) * 32] = r[i];
        }
    }
}

__global__ __launch_bounds__(256, 2)
void fused_kernel(const float* __restrict__ x_num,
                  const int*   __restrict__ x_cat,
                  const float* __restrict__ W1,
                  const float* __restrict__ b1,
                  const float* __restrict__ b2,
                  const float* __restrict__ emb,
                  const float* __restrict__ gamma,
                  const float* __restrict__ beta,
                  float* __restrict__ out) {
    const int tid  = threadIdx.x;
    const int lane = tid & 31;
    const int warp = tid >> 5;       // 0..7

    // ================= CAT PATH =================
    if (blockIdx.x >= GEMM_CTAS) {
        const int blk2 = blockIdx.x - GEMM_CTAS;
        const float4* g4  = (const float4*)gamma;
        const float4* be4 = (const float4*)beta;
        float4 g0 = g4[lane], g1 = g4[lane + 32];
        float4 e0 = be4[lane], e1 = be4[lane + 32];

        #pragma unroll 1
        for (int it = 0; it < TOK_PER_CAT_CTA / 8; it++) {
            const int tok = blk2 * TOK_PER_CAT_CTA + it * 8 + warp;
            const int b = tok / Q_DIM;
            const int q = tok % Q_DIM;
            const int idx = x_cat[(size_t)b * Q_DIM + q];
            const float4* src = (const float4*)(emb + ((size_t)q * V_DIM + idx) * E_DIM);
            float4 v0 = src[lane];
            float4 v1 = src[lane + 32];

            float sum = v0.x + v0.y + v0.z + v0.w + v1.x + v1.y + v1.z + v1.w;
            float sq  = v0.x * v0.x + v0.y * v0.y + v0.z * v0.z + v0.w * v0.w
                      + v1.x * v1.x + v1.y * v1.y + v1.z * v1.z + v1.w * v1.w;
            #pragma unroll
            for (int off = 16; off > 0; off >>= 1) {
                sum += __shfl_xor_sync(0xFFFFFFFFu, sum, off);
                sq  += __shfl_xor_sync(0xFFFFFFFFu, sq, off);
            }
            const float mu   = sum * (1.0f / 256.0f);
            const float var  = sq * (1.0f / 256.0f) - mu * mu;
            const float rstd = rsqrtf(var + LN_EPS);

            float4 r0, r1;
            r0.x = (v0.x - mu) * rstd * g0.x + e0.x;
            r0.y = (v0.y - mu) * rstd * g0.y + e0.y;
            r0.z = (v0.z - mu) * rstd * g0.z + e0.z;
            r0.w = (v0.w - mu) * rstd * g0.w + e0.w;
            r1.x = (v1.x - mu) * rstd * g1.x + e1.x;
            r1.y = (v1.y - mu) * rstd * g1.y + e1.y;
            r1.z = (v1.z - mu) * rstd * g1.z + e1.z;
            r1.w = (v1.w - mu) * rstd * g1.w + e1.w;

            float4* dst = (float4*)(out + ((size_t)b * 36 + 24 + q) * E_DIM);
            dst[lane] = r0;
            dst[lane + 32] = r1;
        }
        return;
    }

    // ================= GEMM PATH =================
    extern __shared__ char smem[];
    const int p     = blockIdx.x >> 5;   // 0..23
    const int mslot = blockIdx.x & 31;   // 0..31

    float* xs  = (float*)(smem + SM_X);
    float* w1s = (float*)(smem + SM_W1);
    float* b1s = (float*)(smem + SM_B1);
    float* b2s = (float*)(smem + SM_B2);
    float* gs  = (float*)(smem + SM_G);
    float* bes = (float*)(smem + SM_BE);
    float* statb = (float*)(smem + SM_STAT);         // [64][16]
    uint4* afrag = (uint4*)(smem + SM_A);
    uint4* bufs[2] = { (uint4*)(smem + SM_BUF), (uint4*)(smem + SM_BUF + 32768) };

    w1s[tid] = W1[p * 256 + tid];
    b1s[tid] = b1[p * 256 + tid];
    b2s[tid] = b2[p * 256 + tid];
    gs[tid]  = gamma[tid];
    bes[tid] = beta[tid];

    const uint4* w2f = g_W2Tf + (size_t)p * 8192;

    // pre-stage chunks 0 (buf0) and 1 (buf1)
    stage_full(w2f, bufs[0], 0, warp, lane);
    stage_full(w2f, bufs[1], 1, warp, lane);

    float2 b2v[4];
    #pragma unroll
    for (int ntl = 0; ntl < 4; ntl++)
        b2v[ntl] = *(float2*)&b2[p * 256 + warp * 32 + ntl * 8 + (lane & 3) * 2];

    // ---- Tile loop: 4 tiles of 64 rows ----
    for (int t = 0; t < 4; t++) {
        const int m0 = (mslot * 4 + t) * 64;
        // chunk order: bufs currently hold {o0,o1}
        const int par = t & 1;
        const int o0 = par ? 2 : 0, o1 = par ? 3 : 1;
        const int o2 = par ? 0 : 2, o3 = par ? 1 : 3;

        __syncthreads();                 // protect xs/A/stat/bufs from prev tile
        if (tid < 64) xs[tid] = x_num[(size_t)(m0 + tid) * P_DIM + p];
        __syncthreads();                 // xs ready (and pre-staged bufs at t=0)

        // ---- Prologue: gelu -> A frags (warp covers ks = warp, warp+8) ----
        #pragma unroll
        for (int kk = 0; kk < 2; kk++) {
            const int ks = warp + kk * 8;
            const int kbase = ks * 16 + (lane & 3) * 2;
            #pragma unroll
            for (int mti = 0; mti < 4; mti++) {
                const float xm0 = xs[mti * 16 + (lane >> 2)];
                const float xm1 = xs[mti * 16 + (lane >> 2) + 8];
                uint32_t r[4];
                #pragma unroll
                for (int reg = 0; reg < 4; reg++) {
                    const float xm = (reg & 1) ? xm1 : xm0;
                    const int k = kbase + (reg & 2) * 4;
                    float h0 = fast_gelu(fmaf(xm, w1s[k],     b1s[k]));
                    float h1 = fast_gelu(fmaf(xm, w1s[k + 1], b1s[k + 1]));
                    __half2 hv = __floats2half2_rn(h0, h1);
                    r[reg] = *reinterpret_cast<uint32_t*>(&hv);
                }
                afrag[(ks * 4 + mti) * 32 + lane] = make_uint4(r[0], r[1], r[2], r[3]);
            }
        }
        __syncthreads();                 // A ready

        float acc[4][4][4];
        #pragma unroll
        for (int i = 0; i < 4; i++)
            #pragma unroll
            for (int j = 0; j < 4; j++)
                #pragma unroll
                for (int r = 0; r < 4; r++) acc[i][j][r] = 0.f;

        mma_chunk<false>(acc, afrag, bufs[o0 & 1], o0, warp, lane, w2f, nullptr, 0);
        __syncthreads();                 // all warps done reading buf[o0&1]
        mma_chunk<true >(acc, afrag, bufs[o1 & 1], o1, warp, lane, w2f, bufs[o2 & 1], o2);
        __syncthreads();                 // buf[o2&1] staged; all done reading buf[o1&1]
        mma_chunk<true >(acc, afrag, bufs[o2 & 1], o2, warp, lane, w2f, bufs[o3 & 1], o3);
        __syncthreads();                 // buf[o3&1] staged
        mma_chunk<false>(acc, afrag, bufs[o3 & 1], o3, warp, lane, w2f, nullptr, 0);

        // ---- Epilogue: +b2, LayerNorm ----
        #pragma unroll
        for (int mti = 0; mti < 4; mti++)
            #pragma unroll
            for (int ntl = 0; ntl < 4; ntl++) {
                acc[mti][ntl][0] += b2v[ntl].x;
                acc[mti][ntl][1] += b2v[ntl].y;
                acc[mti][ntl][2] += b2v[ntl].x;
                acc[mti][ntl][3] += b2v[ntl].y;
            }

        #pragma unroll
        for (int mti = 0; mti < 4; mti++)
            #pragma unroll
            for (int h = 0; h < 2; h++) {
                float s = 0.f, q = 0.f;
                #pragma unroll
                for (int ntl = 0; ntl < 4; ntl++) {
                    float v0 = acc[mti][ntl][h * 2];
                    float v1 = acc[mti][ntl][h * 2 + 1];
                    s += v0 + v1;
                    q += v0 * v0 + v1 * v1;
                }
                s += __shfl_xor_sync(0xFFFFFFFFu, s, 1);
                q += __shfl_xor_sync(0xFFFFFFFFu, q, 1);
                s += __shfl_xor_sync(0xFFFFFFFFu, s, 2);
                q += __shfl_xor_sync(0xFFFFFFFFu, q, 2);
                if ((lane & 3) == 0) {
                    const int row = mti * 16 + (lane >> 2) + h * 8;
                    *(float2*)&statb[row * 16 + warp * 2] = make_float2(s, q);
                }
            }
        __syncthreads();                 // stats visible

        #pragma unroll
        for (int mti = 0; mti < 4; mti++)
            #pragma unroll
            for (int h = 0; h < 2; h++) {
                const int row = mti * 16 + (lane >> 2) + h * 8;
                float sum = 0.f, sq = 0.f;
                #pragma unroll
                for (int j = 0; j < 4; j++) {
                    float4 v = *(float4*)&statb[row * 16 + j * 4];
                    sum += v.x + v.z;
                    sq  += v.y + v.w;
                }
                const float mu   = sum * (1.0f / 256.0f);
                const float var  = sq * (1.0f / 256.0f) - mu * mu;
                const float rstd = rsqrtf(var + LN_EPS);

                float* orow = out + (((size_t)(m0 + row) * 36 + p) * 256);
                #pragma unroll
                for (int ntl = 0; ntl < 4; ntl++) {
                    const int col = warp * 32 + ntl * 8 + (lane & 3) * 2;
                    const float2 gvv = *(float2*)&gs[col];
                    const float2 bvv = *(float2*)&bes[col];
                    float2 r;
                    r.x = (acc[mti][ntl][h * 2]     - mu) * rstd * gvv.x + bvv.x;
                    r.y = (acc[mti][ntl][h * 2 + 1] - mu) * rstd * gvv.y + bvv.y;
                    *(float2*)&orow[col] = r;
                }
            }
    }
}

// ===================== Launch =====================
extern "C" void kernel_launch(void* const* d_in, const int* in_sizes, int n_in,
                              void* d_out, int out_size) {
    const float* x_num = (const float*)d_in[0];
    const int*   x_cat = (const int*)d_in[1];
    const float* W1    = (const float*)d_in[2];
    const float* b1    = (const float*)d_in[3];
    const float* W2    = (const float*)d_in[4];
    const float* b2    = (const float*)d_in[5];
    const float* emb   = (const float*)d_in[6];
    const float* gamma = (const float*)d_in[7];
    const float* beta  = (const float*)d_in[8];
    float* out = (float*)d_out;

    cudaFuncSetAttribute(fused_kernel,
                         cudaFuncAttributeMaxDynamicSharedMemorySize, GEMM_SMEM);

    w2t_kernel<<<dim3(8, 8, 24), dim3(32, 8)>>>(W2);
    pack_kernel<<<P_DIM, 256>>>();
    fused_kernel<<<GEMM_CTAS + CAT_CTAS, 256, GEMM_SMEM>>>(
        x_num, x_cat, W1, b1, b2, emb, gamma, beta, out);
}